// round 2
// baseline (speedup 1.0000x reference)
#include <cuda_runtime.h>
#include <cuda_bf16.h>
#include <math.h>

// Problem constants
#define BB   8
#define TT   1024
#define DM   1024
#define NH   16
#define HS   64
#define MM   (BB*TT)          // 8192 rows
#define DFF  (4*DM)           // 4096

// ---------------- scratch (device globals; no allocation allowed) ------------
__device__ float g_h  [MM*DM];   // LN output (reused for LN2)
__device__ float g_q  [MM*DM];
__device__ float g_k  [MM*DM];
__device__ float g_v  [MM*DM];
__device__ float g_att[MM*DM];
__device__ float g_x1 [MM*DM];
__device__ float g_mid[MM*DFF];

// ---------------- LayerNorm ------------------------------------------------
__global__ __launch_bounds__(256) void ln_kernel(
    const float* __restrict__ x, const float* __restrict__ g,
    const float* __restrict__ b, float* __restrict__ out)
{
    const int row = blockIdx.x;
    const int tid = threadIdx.x;
    const float4* xr = (const float4*)(x + (size_t)row * DM);
    float4 v = xr[tid];
    float s  = v.x + v.y + v.z + v.w;
    float sq = v.x*v.x + v.y*v.y + v.z*v.z + v.w*v.w;
    #pragma unroll
    for (int off = 16; off; off >>= 1) {
        s  += __shfl_xor_sync(0xffffffffu, s,  off);
        sq += __shfl_xor_sync(0xffffffffu, sq, off);
    }
    __shared__ float ss[8], ssq[8];
    const int w = tid >> 5, lane = tid & 31;
    if (lane == 0) { ss[w] = s; ssq[w] = sq; }
    __syncthreads();
    float tot = 0.f, totq = 0.f;
    #pragma unroll
    for (int i = 0; i < 8; i++) { tot += ss[i]; totq += ssq[i]; }
    const float mean = tot * (1.f / DM);
    const float var  = totq * (1.f / DM) - mean * mean;
    const float inv  = rsqrtf(var + 1e-5f);
    float4 gg = ((const float4*)g)[tid];
    float4 bb = ((const float4*)b)[tid];
    float4 o;
    o.x = (v.x - mean) * inv * gg.x + bb.x;
    o.y = (v.y - mean) * inv * gg.y + bb.y;
    o.z = (v.z - mean) * inv * gg.z + bb.z;
    o.w = (v.w - mean) * inv * gg.w + bb.w;
    ((float4*)(out + (size_t)row * DM))[tid] = o;
}

// ---------------- SGEMM: C = A[MxK] @ B[KxN] (+bias)(+residual)(relu) -------
// MODE 0: plain   MODE 1: +bias +residual   MODE 2: +bias, relu
template<int MODE>
__global__ __launch_bounds__(256) void sgemm128(
    const float* __restrict__ A, const float* __restrict__ B,
    const float* __restrict__ bias, const float* __restrict__ R,
    float* __restrict__ C, int M, int N, int K)
{
    __shared__ float As[8][128];
    __shared__ float Bs[8][128];
    const int tid = threadIdx.x;
    const int tx = tid & 15, ty = tid >> 4;
    const float* Ab = A + (size_t)blockIdx.y * 128 * K;
    const float* Bb = B + blockIdx.x * 128;

    float acc[8][8];
    #pragma unroll
    for (int i = 0; i < 8; i++)
        #pragma unroll
        for (int j = 0; j < 8; j++) acc[i][j] = 0.f;

    const int aRow = tid >> 1, aCol = (tid & 1) * 4;
    const int bRow = tid >> 5, bCol = (tid & 31) * 4;

    for (int k0 = 0; k0 < K; k0 += 8) {
        float4 av = *(const float4*)(Ab + (size_t)aRow * K + k0 + aCol);
        As[aCol+0][aRow] = av.x;
        As[aCol+1][aRow] = av.y;
        As[aCol+2][aRow] = av.z;
        As[aCol+3][aRow] = av.w;
        *(float4*)&Bs[bRow][bCol] = *(const float4*)(Bb + (size_t)(k0 + bRow) * N + bCol);
        __syncthreads();
        #pragma unroll
        for (int kk = 0; kk < 8; kk++) {
            float4 a0 = *(const float4*)&As[kk][ty * 8];
            float4 a1 = *(const float4*)&As[kk][ty * 8 + 4];
            float4 b0 = *(const float4*)&Bs[kk][tx * 8];
            float4 b1 = *(const float4*)&Bs[kk][tx * 8 + 4];
            float ra[8] = {a0.x, a0.y, a0.z, a0.w, a1.x, a1.y, a1.z, a1.w};
            float rb[8] = {b0.x, b0.y, b0.z, b0.w, b1.x, b1.y, b1.z, b1.w};
            #pragma unroll
            for (int i = 0; i < 8; i++)
                #pragma unroll
                for (int j = 0; j < 8; j++)
                    acc[i][j] += ra[i] * rb[j];
        }
        __syncthreads();
    }

    #pragma unroll
    for (int i = 0; i < 8; i++) {
        const int gr = blockIdx.y * 128 + ty * 8 + i;
        const int gc = blockIdx.x * 128 + tx * 8;
        float* cp = C + (size_t)gr * N + gc;
        float vals[8];
        #pragma unroll
        for (int j = 0; j < 8; j++) {
            float vv = acc[i][j];
            if (MODE != 0) vv += bias[gc + j];
            if (MODE == 1) vv += R[(size_t)gr * N + gc + j];
            if (MODE == 2) vv = fmaxf(vv, 0.f);
            vals[j] = vv;
        }
        *(float4*)cp       = make_float4(vals[0], vals[1], vals[2], vals[3]);
        *(float4*)(cp + 4) = make_float4(vals[4], vals[5], vals[6], vals[7]);
    }
}

// ---------------- Flash attention (causal, scale = 1/sqrt(D) = 1/32) --------
// grid: (T/128, H, B), block: 128 threads; one thread = one query row.
__global__ __launch_bounds__(128, 1) void attn_kernel(
    const float* __restrict__ Q, const float* __restrict__ K,
    const float* __restrict__ V, float* __restrict__ O)
{
    __shared__ float Ks[32][64];
    __shared__ float Vs[32][64];
    __shared__ float Ps[128][33];   // padded: bank-conflict-free per-thread rows

    const int tid = threadIdx.x;
    const int qt = blockIdx.x, hh = blockIdx.y, bb = blockIdx.z;
    const int qi = qt * 128 + tid;  // global query row within T
    const size_t base = (size_t)bb * TT * DM + (size_t)hh * HS;

    const float4* qr = (const float4*)(Q + base + (size_t)qi * DM);
    float4 q4[16], o4[16];
    #pragma unroll
    for (int i = 0; i < 16; i++) { q4[i] = qr[i]; o4[i] = make_float4(0.f, 0.f, 0.f, 0.f); }

    float m = -1e30f, l = 0.f;
    const int nkt = qt * 4 + 4;     // key tiles of 32 covering [0, qt*128+128)

    for (int kt = 0; kt < nkt; kt++) {
        __syncthreads();
        #pragma unroll
        for (int i = 0; i < 4; i++) {
            const int slot = i * 128 + tid;          // 512 float4 slots per tile
            const int r = slot >> 4, c = slot & 15;
            const size_t gidx = base + (size_t)(kt * 32 + r) * DM + (size_t)c * 4;
            ((float4*)Ks)[slot] = *(const float4*)(K + gidx);
            ((float4*)Vs)[slot] = *(const float4*)(V + gidx);
        }
        __syncthreads();

        float tmax = -1e30f;
        #pragma unroll 4
        for (int j = 0; j < 32; j++) {
            const float4* kr = (const float4*)&Ks[j][0];
            float s = 0.f;
            #pragma unroll
            for (int d = 0; d < 16; d++) {
                float4 kk = kr[d];
                s += q4[d].x * kk.x + q4[d].y * kk.y + q4[d].z * kk.z + q4[d].w * kk.w;
            }
            s *= 0.03125f;                 // 1/sqrt(1024)
            if (kt * 32 + j > qi) s = -1e30f;
            Ps[tid][j] = s;
            tmax = fmaxf(tmax, s);
        }

        const float mnew = fmaxf(m, tmax);
        const float corr = __expf(m - mnew);
        l *= corr;
        #pragma unroll
        for (int i = 0; i < 16; i++) {
            o4[i].x *= corr; o4[i].y *= corr; o4[i].z *= corr; o4[i].w *= corr;
        }
        #pragma unroll 4
        for (int j = 0; j < 32; j++) {
            const float p = __expf(Ps[tid][j] - mnew);
            Ps[tid][j] = p;
            l += p;
        }
        m = mnew;

        #pragma unroll 2
        for (int j = 0; j < 32; j++) {
            const float p = Ps[tid][j];
            const float4* vr = (const float4*)&Vs[j][0];
            #pragma unroll
            for (int d = 0; d < 16; d++) {
                float4 vv = vr[d];
                o4[d].x += p * vv.x; o4[d].y += p * vv.y;
                o4[d].z += p * vv.z; o4[d].w += p * vv.w;
            }
        }
    }

    const float inv = 1.f / l;
    float4* orow = (float4*)(O + base + (size_t)qi * DM);
    #pragma unroll
    for (int i = 0; i < 16; i++)
        orow[i] = make_float4(o4[i].x * inv, o4[i].y * inv, o4[i].z * inv, o4[i].w * inv);
}

// ---------------- launch ----------------------------------------------------
extern "C" void kernel_launch(void* const* d_in, const int* in_sizes, int n_in,
                              void* d_out, int out_size)
{
    const float* x    = (const float*)d_in[0];
    const float* Wq   = (const float*)d_in[1];
    const float* Wk   = (const float*)d_in[2];
    const float* Wv   = (const float*)d_in[3];
    const float* Wo   = (const float*)d_in[4];
    const float* bo   = (const float*)d_in[5];
    const float* W1   = (const float*)d_in[6];
    const float* b1   = (const float*)d_in[7];
    const float* W2   = (const float*)d_in[8];
    const float* b2   = (const float*)d_in[9];
    const float* ln1g = (const float*)d_in[10];
    const float* ln1b = (const float*)d_in[11];
    const float* ln2g = (const float*)d_in[12];
    const float* ln2b = (const float*)d_in[13];
    float* out = (float*)d_out;

    float *h, *q, *k, *v, *att, *x1, *mid;
    cudaGetSymbolAddress((void**)&h,   g_h);
    cudaGetSymbolAddress((void**)&q,   g_q);
    cudaGetSymbolAddress((void**)&k,   g_k);
    cudaGetSymbolAddress((void**)&v,   g_v);
    cudaGetSymbolAddress((void**)&att, g_att);
    cudaGetSymbolAddress((void**)&x1,  g_x1);
    cudaGetSymbolAddress((void**)&mid, g_mid);

    // 1) LN1
    ln_kernel<<<MM, 256>>>(x, ln1g, ln1b, h);

    // 2) Q,K,V projections
    dim3 g1(DM / 128, MM / 128);
    sgemm128<0><<<g1, 256>>>(h, Wq, nullptr, nullptr, q, MM, DM, DM);
    sgemm128<0><<<g1, 256>>>(h, Wk, nullptr, nullptr, k, MM, DM, DM);
    sgemm128<0><<<g1, 256>>>(h, Wv, nullptr, nullptr, v, MM, DM, DM);

    // 3) causal flash attention -> att (already [B,T,D] head-concat layout)
    dim3 ga(TT / 128, NH, BB);
    attn_kernel<<<ga, 128>>>(q, k, v, att);

    // 4) x1 = x + att @ Wo + bo
    sgemm128<1><<<g1, 256>>>(att, Wo, bo, x, x1, MM, DM, DM);

    // 5) LN2
    ln_kernel<<<MM, 256>>>(x1, ln2g, ln2b, h);

    // 6) mid = relu(h @ W1 + b1)
    dim3 g2(DFF / 128, MM / 128);
    sgemm128<2><<<g2, 256>>>(h, W1, b1, nullptr, mid, MM, DFF, DM);

    // 7) out = x1 + mid @ W2 + b2
    sgemm128<1><<<g1, 256>>>(mid, W2, b2, x1, out, MM, DM, DFF);
}

// round 4
// speedup vs baseline: 2.2313x; 2.2313x over previous
#include <cuda_runtime.h>
#include <cuda_bf16.h>
#include <math.h>
#include <stdint.h>

// Problem constants
#define BB   8
#define TT   1024
#define DM   1024
#define NH   16
#define HS   64
#define MM   (BB*TT)          // 8192 rows
#define DFF  (4*DM)           // 4096

// ---------------- scratch (device globals; no allocation allowed) ------------
__device__ float g_h  [MM*DM];
__device__ float g_q  [MM*DM];
__device__ float g_k  [MM*DM];
__device__ float g_v  [MM*DM];
__device__ float g_att[MM*DM];
__device__ float g_x1 [MM*DM];
__device__ float g_mid[(size_t)MM*DFF];

// ---------------- helpers ----------------------------------------------------
__device__ __forceinline__ float to_tf32(float x) {
    float r; asm("cvt.rna.tf32.f32 %0, %1;" : "=f"(r) : "f"(x)); return r;
}
__device__ __forceinline__ void mma_m16n8k8(float* d, const uint32_t* a, const uint32_t* b) {
    asm volatile(
        "mma.sync.aligned.m16n8k8.row.col.f32.tf32.tf32.f32 "
        "{%0,%1,%2,%3}, {%4,%5,%6,%7}, {%8,%9}, {%0,%1,%2,%3};"
        : "+f"(d[0]), "+f"(d[1]), "+f"(d[2]), "+f"(d[3])
        : "r"(a[0]), "r"(a[1]), "r"(a[2]), "r"(a[3]), "r"(b[0]), "r"(b[1]));
}

// smem geometry (floats)
#define AS_STRIDE 36          // 32 + 4 pad  -> frag loads conflict-free
#define BS_STRIDE 132         // 128 + 4 pad -> frag loads conflict-free
#define AS_BUF    (128 * AS_STRIDE)   // 4608
#define BS_BUF    (32  * BS_STRIDE)   // 4224
#define SM_FLOATS (2*AS_BUF + 2*BS_BUF)
#define SM_BYTES  (SM_FLOATS * 4)     // 70656

// ---------------- LayerNorm ------------------------------------------------
__global__ __launch_bounds__(256) void ln_kernel(
    const float* __restrict__ x, const float* __restrict__ g,
    const float* __restrict__ b, float* __restrict__ out)
{
    const int row = blockIdx.x;
    const int tid = threadIdx.x;
    const float4* xr = (const float4*)(x + (size_t)row * DM);
    float4 v = xr[tid];
    float s  = v.x + v.y + v.z + v.w;
    float sq = v.x*v.x + v.y*v.y + v.z*v.z + v.w*v.w;
    #pragma unroll
    for (int off = 16; off; off >>= 1) {
        s  += __shfl_xor_sync(0xffffffffu, s,  off);
        sq += __shfl_xor_sync(0xffffffffu, sq, off);
    }
    __shared__ float ss[8], ssq[8];
    const int w = tid >> 5, lane = tid & 31;
    if (lane == 0) { ss[w] = s; ssq[w] = sq; }
    __syncthreads();
    float tot = 0.f, totq = 0.f;
    #pragma unroll
    for (int i = 0; i < 8; i++) { tot += ss[i]; totq += ssq[i]; }
    const float mean = tot * (1.f / DM);
    const float var  = totq * (1.f / DM) - mean * mean;
    const float inv  = rsqrtf(var + 1e-5f);
    float4 gg = ((const float4*)g)[tid];
    float4 bb = ((const float4*)b)[tid];
    float4 o;
    o.x = (v.x - mean) * inv * gg.x + bb.x;
    o.y = (v.y - mean) * inv * gg.y + bb.y;
    o.z = (v.z - mean) * inv * gg.z + bb.z;
    o.w = (v.w - mean) * inv * gg.w + bb.w;
    ((float4*)(out + (size_t)row * DM))[tid] = o;
}

// ---------------- tf32 tensor-core GEMM --------------------------------------
// C = A[M x K] @ W[K x N] (weights in native [K,N] row-major — B frag is K x N).
// MODE 0: plain (z selects among 3 weight/output pairs)
// MODE 1: +bias +residual     MODE 2: +bias, relu
template<int MODE>
__global__ __launch_bounds__(256) void tgemm_kernel(
    const float* __restrict__ A,
    const float* __restrict__ W0, const float* __restrict__ W1w, const float* __restrict__ W2w,
    const float* __restrict__ bias, const float* __restrict__ R,
    float* __restrict__ C0, float* __restrict__ C1, float* __restrict__ C2,
    int K, int Nw)
{
    extern __shared__ float sm[];
    float* As = sm;                 // [2][128][AS_STRIDE]
    float* Bs = sm + 2 * AS_BUF;    // [2][32][BS_STRIDE]

    const int tid  = threadIdx.x;
    const int wid  = tid >> 5, lane = tid & 31;
    const int warpM = wid >> 2, warpN = wid & 3;   // 2 x 4 warp grid
    const int z = blockIdx.z;
    const float* Wp = (z == 0) ? W0 : (z == 1) ? W1w : W2w;
    float* C = (z == 0) ? C0 : (z == 1) ? C1 : C2;

    const int mBase = blockIdx.y * 128;
    const int nBase = blockIdx.x * 128;
    const float* Aptr = A  + (size_t)mBase * K;
    const float* Bptr = Wp + nBase;

    float acc[4][4][4];
    #pragma unroll
    for (int i = 0; i < 4; i++)
        #pragma unroll
        for (int j = 0; j < 4; j++)
            #pragma unroll
            for (int t = 0; t < 4; t++) acc[i][j][t] = 0.f;

    float4 aReg[4], bReg[4];

    // ---- global loads into regs for chunk at k0 ----
    auto LDG = [&](int k0) {
        #pragma unroll
        for (int i = 0; i < 4; i++) {
            const int idx = i * 256 + tid;
            const int r = idx >> 3, c = idx & 7;            // A: 128 x 8 float4
            aReg[i] = *(const float4*)(Aptr + (size_t)r * K + k0 + c * 4);
        }
        #pragma unroll
        for (int i = 0; i < 4; i++) {
            const int idx = i * 256 + tid;
            const int r = idx >> 5, c = idx & 31;           // B: 32 x 32 float4
            bReg[i] = *(const float4*)(Bptr + (size_t)(k0 + r) * Nw + c * 4);
        }
    };
    // ---- store staged regs to smem buffer b (tf32-rounded) ----
    auto STS = [&](int b) {
        float* Ab = As + b * AS_BUF;
        float* Bb = Bs + b * BS_BUF;
        #pragma unroll
        for (int i = 0; i < 4; i++) {
            const int idx = i * 256 + tid;
            const int r = idx >> 3, c = idx & 7;
            float4 v = aReg[i];
            v.x = to_tf32(v.x); v.y = to_tf32(v.y);
            v.z = to_tf32(v.z); v.w = to_tf32(v.w);
            *(float4*)(Ab + r * AS_STRIDE + c * 4) = v;
        }
        #pragma unroll
        for (int i = 0; i < 4; i++) {
            const int idx = i * 256 + tid;
            const int r = idx >> 5, c = idx & 31;
            float4 v = bReg[i];
            v.x = to_tf32(v.x); v.y = to_tf32(v.y);
            v.z = to_tf32(v.z); v.w = to_tf32(v.w);
            *(float4*)(Bb + r * BS_STRIDE + c * 4) = v;
        }
    };
    // ---- tensor compute on buffer b ----
    auto COMPUTE = [&](int b) {
        const float* Ab = As + b * AS_BUF;
        const float* Bb = Bs + b * BS_BUF;
        #pragma unroll
        for (int kk = 0; kk < 4; kk++) {
            uint32_t af[4][4], bf[4][2];
            const int c0 = kk * 8 + (lane & 3);
            const int r0 = lane >> 2;
            #pragma unroll
            for (int mi = 0; mi < 4; mi++) {
                const int row = warpM * 64 + mi * 16 + r0;
                af[mi][0] = __float_as_uint(Ab[row * AS_STRIDE + c0]);
                af[mi][1] = __float_as_uint(Ab[(row + 8) * AS_STRIDE + c0]);
                af[mi][2] = __float_as_uint(Ab[row * AS_STRIDE + c0 + 4]);
                af[mi][3] = __float_as_uint(Ab[(row + 8) * AS_STRIDE + c0 + 4]);
            }
            const int kr = kk * 8 + (lane & 3);
            #pragma unroll
            for (int ni = 0; ni < 4; ni++) {
                const int col = warpN * 32 + ni * 8 + (lane >> 2);
                bf[ni][0] = __float_as_uint(Bb[kr * BS_STRIDE + col]);
                bf[ni][1] = __float_as_uint(Bb[(kr + 4) * BS_STRIDE + col]);
            }
            #pragma unroll
            for (int mi = 0; mi < 4; mi++)
                #pragma unroll
                for (int ni = 0; ni < 4; ni++)
                    mma_m16n8k8(acc[mi][ni], af[mi], bf[ni]);
        }
    };

    const int nch = K / 32;
    LDG(0); STS(0);
    __syncthreads();
    for (int c = 0; c < nch; c++) {
        const int b = c & 1;
        if (c + 1 < nch) LDG((c + 1) * 32);
        COMPUTE(b);
        if (c + 1 < nch) STS(b ^ 1);
        __syncthreads();
    }

    // ---- epilogue ----
    #pragma unroll
    for (int mi = 0; mi < 4; mi++) {
        #pragma unroll
        for (int ni = 0; ni < 4; ni++) {
            const int gr = mBase + warpM * 64 + mi * 16 + (lane >> 2);
            const int gc = nBase + warpN * 32 + ni * 8 + (lane & 3) * 2;
            float v0 = acc[mi][ni][0], v1 = acc[mi][ni][1];
            float v2 = acc[mi][ni][2], v3 = acc[mi][ni][3];
            if (MODE != 0) {
                const float b0 = bias[gc], b1 = bias[gc + 1];
                v0 += b0; v1 += b1; v2 += b0; v3 += b1;
            }
            if (MODE == 1) {
                const float* r0p = R + (size_t)gr * Nw + gc;
                const float* r1p = R + (size_t)(gr + 8) * Nw + gc;
                v0 += r0p[0]; v1 += r0p[1]; v2 += r1p[0]; v3 += r1p[1];
            }
            if (MODE == 2) {
                v0 = fmaxf(v0, 0.f); v1 = fmaxf(v1, 0.f);
                v2 = fmaxf(v2, 0.f); v3 = fmaxf(v3, 0.f);
            }
            *(float2*)(C + (size_t)gr * Nw + gc)       = make_float2(v0, v1);
            *(float2*)(C + (size_t)(gr + 8) * Nw + gc) = make_float2(v2, v3);
        }
    }
}

// ---------------- Flash attention (causal, scale = 1/sqrt(D) = 1/32) --------
__global__ __launch_bounds__(128, 1) void attn_kernel(
    const float* __restrict__ Q, const float* __restrict__ K,
    const float* __restrict__ V, float* __restrict__ O)
{
    __shared__ float Ks[32][64];
    __shared__ float Vs[32][64];
    __shared__ float Ps[128][33];

    const int tid = threadIdx.x;
    const int qt = blockIdx.x, hh = blockIdx.y, bb = blockIdx.z;
    const int qi = qt * 128 + tid;
    const size_t base = (size_t)bb * TT * DM + (size_t)hh * HS;

    const float4* qr = (const float4*)(Q + base + (size_t)qi * DM);
    float4 q4[16], o4[16];
    #pragma unroll
    for (int i = 0; i < 16; i++) { q4[i] = qr[i]; o4[i] = make_float4(0.f, 0.f, 0.f, 0.f); }

    float m = -1e30f, l = 0.f;
    const int nkt = qt * 4 + 4;

    for (int kt = 0; kt < nkt; kt++) {
        __syncthreads();
        #pragma unroll
        for (int i = 0; i < 4; i++) {
            const int slot = i * 128 + tid;
            const int r = slot >> 4, c = slot & 15;
            const size_t gidx = base + (size_t)(kt * 32 + r) * DM + (size_t)c * 4;
            ((float4*)Ks)[slot] = *(const float4*)(K + gidx);
            ((float4*)Vs)[slot] = *(const float4*)(V + gidx);
        }
        __syncthreads();

        float tmax = -1e30f;
        #pragma unroll 4
        for (int j = 0; j < 32; j++) {
            const float4* kr = (const float4*)&Ks[j][0];
            float s = 0.f;
            #pragma unroll
            for (int d = 0; d < 16; d++) {
                float4 kk = kr[d];
                s += q4[d].x * kk.x + q4[d].y * kk.y + q4[d].z * kk.z + q4[d].w * kk.w;
            }
            s *= 0.03125f;
            if (kt * 32 + j > qi) s = -1e30f;
            Ps[tid][j] = s;
            tmax = fmaxf(tmax, s);
        }

        const float mnew = fmaxf(m, tmax);
        const float corr = __expf(m - mnew);
        l *= corr;
        #pragma unroll
        for (int i = 0; i < 16; i++) {
            o4[i].x *= corr; o4[i].y *= corr; o4[i].z *= corr; o4[i].w *= corr;
        }
        #pragma unroll 4
        for (int j = 0; j < 32; j++) {
            const float p = __expf(Ps[tid][j] - mnew);
            Ps[tid][j] = p;
            l += p;
        }
        m = mnew;

        #pragma unroll 2
        for (int j = 0; j < 32; j++) {
            const float p = Ps[tid][j];
            const float4* vr = (const float4*)&Vs[j][0];
            #pragma unroll
            for (int d = 0; d < 16; d++) {
                float4 vv = vr[d];
                o4[d].x += p * vv.x; o4[d].y += p * vv.y;
                o4[d].z += p * vv.z; o4[d].w += p * vv.w;
            }
        }
    }

    const float inv = 1.f / l;
    float4* orow = (float4*)(O + base + (size_t)qi * DM);
    #pragma unroll
    for (int i = 0; i < 16; i++)
        orow[i] = make_float4(o4[i].x * inv, o4[i].y * inv, o4[i].z * inv, o4[i].w * inv);
}

// ---------------- launch ----------------------------------------------------
extern "C" void kernel_launch(void* const* d_in, const int* in_sizes, int n_in,
                              void* d_out, int out_size)
{
    const float* x    = (const float*)d_in[0];
    const float* Wq   = (const float*)d_in[1];
    const float* Wk   = (const float*)d_in[2];
    const float* Wv   = (const float*)d_in[3];
    const float* Wo   = (const float*)d_in[4];
    const float* bo   = (const float*)d_in[5];
    const float* W1   = (const float*)d_in[6];
    const float* b1   = (const float*)d_in[7];
    const float* W2   = (const float*)d_in[8];
    const float* b2   = (const float*)d_in[9];
    const float* ln1g = (const float*)d_in[10];
    const float* ln1b = (const float*)d_in[11];
    const float* ln2g = (const float*)d_in[12];
    const float* ln2b = (const float*)d_in[13];
    float* out = (float*)d_out;

    float *h, *q, *k, *v, *att, *x1, *mid;
    cudaGetSymbolAddress((void**)&h,   g_h);
    cudaGetSymbolAddress((void**)&q,   g_q);
    cudaGetSymbolAddress((void**)&k,   g_k);
    cudaGetSymbolAddress((void**)&v,   g_v);
    cudaGetSymbolAddress((void**)&att, g_att);
    cudaGetSymbolAddress((void**)&x1,  g_x1);
    cudaGetSymbolAddress((void**)&mid, g_mid);

    cudaFuncSetAttribute(tgemm_kernel<0>, cudaFuncAttributeMaxDynamicSharedMemorySize, SM_BYTES);
    cudaFuncSetAttribute(tgemm_kernel<1>, cudaFuncAttributeMaxDynamicSharedMemorySize, SM_BYTES);
    cudaFuncSetAttribute(tgemm_kernel<2>, cudaFuncAttributeMaxDynamicSharedMemorySize, SM_BYTES);

    // 1) LN1
    ln_kernel<<<MM, 256>>>(x, ln1g, ln1b, h);

    // 2) fused Q,K,V projections (grid.z selects weight/output)
    dim3 gqkv(DM / 128, MM / 128, 3);
    tgemm_kernel<0><<<gqkv, 256, SM_BYTES>>>(h, Wq, Wk, Wv, nullptr, nullptr,
                                             q, k, v, DM, DM);

    // 3) causal flash attention
    dim3 ga(TT / 128, NH, BB);
    attn_kernel<<<ga, 128>>>(q, k, v, att);

    // 4) x1 = x + att @ Wo + bo
    dim3 g1(DM / 128, MM / 128, 1);
    tgemm_kernel<1><<<g1, 256, SM_BYTES>>>(att, Wo, Wo, Wo, bo, x,
                                           x1, x1, x1, DM, DM);

    // 5) LN2
    ln_kernel<<<MM, 256>>>(x1, ln2g, ln2b, h);

    // 6) mid = relu(h @ W1 + b1)
    dim3 g2(DFF / 128, MM / 128, 1);
    tgemm_kernel<2><<<g2, 256, SM_BYTES>>>(h, W1, W1, W1, b1, nullptr,
                                           mid, mid, mid, DM, DFF);

    // 7) out = x1 + mid @ W2 + b2
    tgemm_kernel<1><<<g1, 256, SM_BYTES>>>(mid, W2, W2, W2, b2, x1,
                                           out, out, out, DFF, DM);
}

// round 8
// speedup vs baseline: 2.7176x; 1.2179x over previous
#include <cuda_runtime.h>
#include <cuda_bf16.h>
#include <math.h>
#include <stdint.h>

// Problem constants
#define BB   8
#define TT   1024
#define DM   1024
#define NH   16
#define HS   64
#define MM   (BB*TT)          // 8192 rows
#define DFF  (4*DM)           // 4096

// ---------------- scratch (device globals; no allocation allowed) ------------
__device__ float g_h  [MM*DM];
__device__ float g_q  [MM*DM];
__device__ float g_k  [MM*DM];
__device__ float g_v  [MM*DM];
__device__ float g_att[MM*DM];
__device__ float g_x1 [MM*DM];
__device__ float g_mid[(size_t)MM*DFF];
// tf32-rounded weight copies (layout unchanged: [K,N] row-major)
__device__ float g_rwq[DM*DM];
__device__ float g_rwk[DM*DM];
__device__ float g_rwv[DM*DM];
__device__ float g_rwo[DM*DM];
__device__ float g_rw1[(size_t)DM*DFF];
__device__ float g_rw2[(size_t)DFF*DM];

// ---------------- helpers ----------------------------------------------------
__device__ __forceinline__ float to_tf32(float x) {
    float r; asm("cvt.rna.tf32.f32 %0, %1;" : "=f"(r) : "f"(x)); return r;
}
__device__ __forceinline__ uint32_t smem_u32(const void* p) {
    uint32_t a;
    asm("{ .reg .u64 t; cvta.to.shared.u64 t, %1; cvt.u32.u64 %0, t; }" : "=r"(a) : "l"(p));
    return a;
}
__device__ __forceinline__ void cp16(uint32_t dst, const void* src) {
    asm volatile("cp.async.cg.shared.global [%0], [%1], 16;" :: "r"(dst), "l"(src));
}
__device__ __forceinline__ void cp_commit() {
    asm volatile("cp.async.commit_group;" ::: "memory");
}
template<int N>
__device__ __forceinline__ void cp_wait() {
    asm volatile("cp.async.wait_group %0;" :: "n"(N) : "memory");
}
__device__ __forceinline__ void mma_m16n8k8(float* d, const uint32_t* a, const uint32_t* b) {
    asm volatile(
        "mma.sync.aligned.m16n8k8.row.col.f32.tf32.tf32.f32 "
        "{%0,%1,%2,%3}, {%4,%5,%6,%7}, {%8,%9}, {%0,%1,%2,%3};"
        : "+f"(d[0]), "+f"(d[1]), "+f"(d[2]), "+f"(d[3])
        : "r"(a[0]), "r"(a[1]), "r"(a[2]), "r"(a[3]), "r"(b[0]), "r"(b[1]));
}

// smem geometry (floats). Strides chosen for conflict-free fragment loads:
// A stride 36  (== 4 mod 32): banks 4*(lane>>2) + (lane&3) all distinct
// B stride 264 (== 8 mod 32): banks 8*(k&3) + (lane>>2) all distinct
#define AS_STRIDE 36
#define BS_STRIDE 264
#define A_STAGE   (128 * AS_STRIDE)              // 4608 floats
#define B_STAGE   (32  * BS_STRIDE)              // 8448 floats
#define STAGE_F   (A_STAGE + B_STAGE)            // 13056 floats
#define SM_BYTES  (3 * STAGE_F * 4)              // 156672 bytes

// ---------------- LayerNorm (outputs tf32-rounded) ---------------------------
__global__ __launch_bounds__(256) void ln_kernel(
    const float* __restrict__ x, const float* __restrict__ g,
    const float* __restrict__ b, float* __restrict__ out)
{
    const int row = blockIdx.x;
    const int tid = threadIdx.x;
    const float4* xr = (const float4*)(x + (size_t)row * DM);
    float4 v = xr[tid];
    float s  = v.x + v.y + v.z + v.w;
    float sq = v.x*v.x + v.y*v.y + v.z*v.z + v.w*v.w;
    #pragma unroll
    for (int off = 16; off; off >>= 1) {
        s  += __shfl_xor_sync(0xffffffffu, s,  off);
        sq += __shfl_xor_sync(0xffffffffu, sq, off);
    }
    __shared__ float ss[8], ssq[8];
    const int w = tid >> 5, lane = tid & 31;
    if (lane == 0) { ss[w] = s; ssq[w] = sq; }
    __syncthreads();
    float tot = 0.f, totq = 0.f;
    #pragma unroll
    for (int i = 0; i < 8; i++) { tot += ss[i]; totq += ssq[i]; }
    const float mean = tot * (1.f / DM);
    const float var  = totq * (1.f / DM) - mean * mean;
    const float inv  = rsqrtf(var + 1e-5f);
    float4 gg = ((const float4*)g)[tid];
    float4 bb = ((const float4*)b)[tid];
    float4 o;
    o.x = to_tf32((v.x - mean) * inv * gg.x + bb.x);
    o.y = to_tf32((v.y - mean) * inv * gg.y + bb.y);
    o.z = to_tf32((v.z - mean) * inv * gg.z + bb.z);
    o.w = to_tf32((v.w - mean) * inv * gg.w + bb.w);
    ((float4*)(out + (size_t)row * DM))[tid] = o;
}

// ---------------- weight rounding (same layout, tf32 rna) --------------------
__global__ __launch_bounds__(256) void round_kernel(
    const float* __restrict__ src, float* __restrict__ dst, int n4)
{
    const int i = blockIdx.x * 256 + threadIdx.x;
    if (i < n4) {
        float4 v = ((const float4*)src)[i];
        v.x = to_tf32(v.x); v.y = to_tf32(v.y);
        v.z = to_tf32(v.z); v.w = to_tf32(v.w);
        ((float4*)dst)[i] = v;
    }
}

// ---------------- tf32 tensor GEMM, 128x256 tile, cp.async 3-stage -----------
// C = A[M x K] @ W[K x N]; A and W pre-rounded to tf32.
// MODE 0: plain (z selects among 3 weight/output pairs)
// MODE 1: +bias +residual     MODE 2: +bias, relu, tf32-round output
template<int MODE>
__global__ __launch_bounds__(256) void tgemm_kernel(
    const float* __restrict__ A,
    const float* __restrict__ W0, const float* __restrict__ W1w, const float* __restrict__ W2w,
    const float* __restrict__ bias, const float* __restrict__ R,
    float* __restrict__ C0, float* __restrict__ C1, float* __restrict__ C2,
    int K, int Nw)
{
    extern __shared__ float sm[];
    const uint32_t smBase = smem_u32(sm);

    const int tid  = threadIdx.x;
    const int wid  = tid >> 5, lane = tid & 31;
    const int warpM = wid >> 2, warpN = wid & 3;   // 2 x 4 warps, warp tile 64x64
    const int z = blockIdx.z;
    const float* Wp = (z == 0) ? W0 : (z == 1) ? W1w : W2w;
    float* C = (z == 0) ? C0 : (z == 1) ? C1 : C2;

    const int mBase = blockIdx.y * 128;
    const int nBase = blockIdx.x * 256;
    const float* Aptr = A  + (size_t)mBase * K;
    const float* Bptr = Wp + nBase;

    float acc[4][8][4];
    #pragma unroll
    for (int i = 0; i < 4; i++)
        #pragma unroll
        for (int j = 0; j < 8; j++)
            #pragma unroll
            for (int t = 0; t < 4; t++) acc[i][j][t] = 0.f;

    // per-thread fill coordinates
    const int arf = tid >> 3, acf = (tid & 7) * 4;    // A: 128 rows x 8 f4/row, 4 iters step 32 rows
    const int brf = tid >> 6, bcf = (tid & 63) * 4;   // B: 32 rows x 64 f4/row, 8 iters step 4 rows

    auto FILL = [&](int c) {
        const int k0 = c * 32;
        const int buf = c % 3;
        const uint32_t aB = smBase + (uint32_t)(buf * STAGE_F) * 4u;
        const uint32_t bB = aB + (uint32_t)A_STAGE * 4u;
        #pragma unroll
        for (int i = 0; i < 4; i++) {
            const int r = arf + i * 32;
            cp16(aB + (uint32_t)(r * AS_STRIDE + acf) * 4u,
                 Aptr + (size_t)r * K + k0 + acf);
        }
        #pragma unroll
        for (int i = 0; i < 8; i++) {
            const int r = brf + i * 4;
            cp16(bB + (uint32_t)(r * BS_STRIDE + bcf) * 4u,
                 Bptr + (size_t)(k0 + r) * Nw + bcf);
        }
        cp_commit();
    };

    auto COMPUTE = [&](int buf) {
        const float* Ab = sm + buf * STAGE_F;
        const float* Bb = Ab + A_STAGE;
        #pragma unroll
        for (int kk = 0; kk < 4; kk++) {
            uint32_t af[4][4], bf[8][2];
            const int c0 = kk * 8 + (lane & 3);
            const int r0 = lane >> 2;
            #pragma unroll
            for (int mi = 0; mi < 4; mi++) {
                const int row = warpM * 64 + mi * 16 + r0;
                af[mi][0] = __float_as_uint(Ab[row * AS_STRIDE + c0]);
                af[mi][1] = __float_as_uint(Ab[(row + 8) * AS_STRIDE + c0]);
                af[mi][2] = __float_as_uint(Ab[row * AS_STRIDE + c0 + 4]);
                af[mi][3] = __float_as_uint(Ab[(row + 8) * AS_STRIDE + c0 + 4]);
            }
            const int kr = kk * 8 + (lane & 3);
            #pragma unroll
            for (int ni = 0; ni < 8; ni++) {
                const int col = warpN * 64 + ni * 8 + (lane >> 2);
                bf[ni][0] = __float_as_uint(Bb[kr * BS_STRIDE + col]);
                bf[ni][1] = __float_as_uint(Bb[(kr + 4) * BS_STRIDE + col]);
            }
            #pragma unroll
            for (int mi = 0; mi < 4; mi++)
                #pragma unroll
                for (int ni = 0; ni < 8; ni++)
                    mma_m16n8k8(acc[mi][ni], af[mi], bf[ni]);
        }
    };

    const int nch = K / 32;
    FILL(0);
    FILL(1);
    for (int c = 0; c < nch; c++) {
        if (c == nch - 1) cp_wait<0>(); else cp_wait<1>();
        __syncthreads();
        if (c + 2 < nch) FILL(c + 2);
        COMPUTE(c % 3);
        __syncthreads();
    }

    // ---- epilogue ----
    #pragma unroll
    for (int mi = 0; mi < 4; mi++) {
        #pragma unroll
        for (int ni = 0; ni < 8; ni++) {
            const int gr = mBase + warpM * 64 + mi * 16 + (lane >> 2);
            const int gc = nBase + warpN * 64 + ni * 8 + (lane & 3) * 2;
            float v0 = acc[mi][ni][0], v1 = acc[mi][ni][1];
            float v2 = acc[mi][ni][2], v3 = acc[mi][ni][3];
            if (MODE != 0) {
                const float b0 = bias[gc], b1 = bias[gc + 1];
                v0 += b0; v1 += b1; v2 += b0; v3 += b1;
            }
            if (MODE == 1) {
                const float* r0p = R + (size_t)gr * Nw + gc;
                const float* r1p = R + (size_t)(gr + 8) * Nw + gc;
                v0 += r0p[0]; v1 += r0p[1]; v2 += r1p[0]; v3 += r1p[1];
            }
            if (MODE == 2) {
                v0 = to_tf32(fmaxf(v0, 0.f)); v1 = to_tf32(fmaxf(v1, 0.f));
                v2 = to_tf32(fmaxf(v2, 0.f)); v3 = to_tf32(fmaxf(v3, 0.f));
            }
            *(float2*)(C + (size_t)gr * Nw + gc)       = make_float2(v0, v1);
            *(float2*)(C + (size_t)(gr + 8) * Nw + gc) = make_float2(v2, v3);
        }
    }
}

// ---------------- Flash attention (causal, scale = 1/sqrt(D) = 1/32) --------
// outputs tf32-rounded (consumed as GEMM A operand)
__global__ __launch_bounds__(128, 1) void attn_kernel(
    const float* __restrict__ Q, const float* __restrict__ K,
    const float* __restrict__ V, float* __restrict__ O)
{
    __shared__ float Ks[32][64];
    __shared__ float Vs[32][64];
    __shared__ float Ps[128][33];

    const int tid = threadIdx.x;
    const int qt = blockIdx.x, hh = blockIdx.y, bb = blockIdx.z;
    const int qi = qt * 128 + tid;
    const size_t base = (size_t)bb * TT * DM + (size_t)hh * HS;

    const float4* qr = (const float4*)(Q + base + (size_t)qi * DM);
    float4 q4[16], o4[16];
    #pragma unroll
    for (int i = 0; i < 16; i++) { q4[i] = qr[i]; o4[i] = make_float4(0.f, 0.f, 0.f, 0.f); }

    float m = -1e30f, l = 0.f;
    const int nkt = qt * 4 + 4;

    for (int kt = 0; kt < nkt; kt++) {
        __syncthreads();
        #pragma unroll
        for (int i = 0; i < 4; i++) {
            const int slot = i * 128 + tid;
            const int r = slot >> 4, c = slot & 15;
            const size_t gidx = base + (size_t)(kt * 32 + r) * DM + (size_t)c * 4;
            ((float4*)Ks)[slot] = *(const float4*)(K + gidx);
            ((float4*)Vs)[slot] = *(const float4*)(V + gidx);
        }
        __syncthreads();

        float tmax = -1e30f;
        #pragma unroll 4
        for (int j = 0; j < 32; j++) {
            const float4* kr = (const float4*)&Ks[j][0];
            float s = 0.f;
            #pragma unroll
            for (int d = 0; d < 16; d++) {
                float4 kk = kr[d];
                s += q4[d].x * kk.x + q4[d].y * kk.y + q4[d].z * kk.z + q4[d].w * kk.w;
            }
            s *= 0.03125f;
            if (kt * 32 + j > qi) s = -1e30f;
            Ps[tid][j] = s;
            tmax = fmaxf(tmax, s);
        }

        const float mnew = fmaxf(m, tmax);
        const float corr = __expf(m - mnew);
        l *= corr;
        #pragma unroll
        for (int i = 0; i < 16; i++) {
            o4[i].x *= corr; o4[i].y *= corr; o4[i].z *= corr; o4[i].w *= corr;
        }
        #pragma unroll 4
        for (int j = 0; j < 32; j++) {
            const float p = __expf(Ps[tid][j] - mnew);
            Ps[tid][j] = p;
            l += p;
        }
        m = mnew;

        #pragma unroll 2
        for (int j = 0; j < 32; j++) {
            const float p = Ps[tid][j];
            const float4* vr = (const float4*)&Vs[j][0];
            #pragma unroll
            for (int d = 0; d < 16; d++) {
                float4 vv = vr[d];
                o4[d].x += p * vv.x; o4[d].y += p * vv.y;
                o4[d].z += p * vv.z; o4[d].w += p * vv.w;
            }
        }
    }

    const float inv = 1.f / l;
    float4* orow = (float4*)(O + base + (size_t)qi * DM);
    #pragma unroll
    for (int i = 0; i < 16; i++)
        orow[i] = make_float4(to_tf32(o4[i].x * inv), to_tf32(o4[i].y * inv),
                              to_tf32(o4[i].z * inv), to_tf32(o4[i].w * inv));
}

// ---------------- launch ----------------------------------------------------
extern "C" void kernel_launch(void* const* d_in, const int* in_sizes, int n_in,
                              void* d_out, int out_size)
{
    const float* x    = (const float*)d_in[0];
    const float* Wq   = (const float*)d_in[1];
    const float* Wk   = (const float*)d_in[2];
    const float* Wv   = (const float*)d_in[3];
    const float* Wo   = (const float*)d_in[4];
    const float* bo   = (const float*)d_in[5];
    const float* W1   = (const float*)d_in[6];
    const float* b1   = (const float*)d_in[7];
    const float* W2   = (const float*)d_in[8];
    const float* b2   = (const float*)d_in[9];
    const float* ln1g = (const float*)d_in[10];
    const float* ln1b = (const float*)d_in[11];
    const float* ln2g = (const float*)d_in[12];
    const float* ln2b = (const float*)d_in[13];
    float* out = (float*)d_out;

    float *h, *q, *k, *v, *att, *x1, *mid;
    float *rwq, *rwk, *rwv, *rwo, *rw1, *rw2;
    cudaGetSymbolAddress((void**)&h,   g_h);
    cudaGetSymbolAddress((void**)&q,   g_q);
    cudaGetSymbolAddress((void**)&k,   g_k);
    cudaGetSymbolAddress((void**)&v,   g_v);
    cudaGetSymbolAddress((void**)&att, g_att);
    cudaGetSymbolAddress((void**)&x1,  g_x1);
    cudaGetSymbolAddress((void**)&mid, g_mid);
    cudaGetSymbolAddress((void**)&rwq, g_rwq);
    cudaGetSymbolAddress((void**)&rwk, g_rwk);
    cudaGetSymbolAddress((void**)&rwv, g_rwv);
    cudaGetSymbolAddress((void**)&rwo, g_rwo);
    cudaGetSymbolAddress((void**)&rw1, g_rw1);
    cudaGetSymbolAddress((void**)&rw2, g_rw2);

    cudaFuncSetAttribute(tgemm_kernel<0>, cudaFuncAttributeMaxDynamicSharedMemorySize, SM_BYTES);
    cudaFuncSetAttribute(tgemm_kernel<1>, cudaFuncAttributeMaxDynamicSharedMemorySize, SM_BYTES);
    cudaFuncSetAttribute(tgemm_kernel<2>, cudaFuncAttributeMaxDynamicSharedMemorySize, SM_BYTES);

    // 0) round weights once (cheap vs GEMMs; graph replays keep it deterministic)
    const int n4d = DM * DM / 4, n4f = DM * DFF / 4;
    round_kernel<<<(n4d + 255) / 256, 256>>>(Wq, rwq, n4d);
    round_kernel<<<(n4d + 255) / 256, 256>>>(Wk, rwk, n4d);
    round_kernel<<<(n4d + 255) / 256, 256>>>(Wv, rwv, n4d);
    round_kernel<<<(n4d + 255) / 256, 256>>>(Wo, rwo, n4d);
    round_kernel<<<(n4f + 255) / 256, 256>>>(W1, rw1, n4f);
    round_kernel<<<(n4f + 255) / 256, 256>>>(W2, rw2, n4f);

    // 1) LN1 (tf32-rounded output)
    ln_kernel<<<MM, 256>>>(x, ln1g, ln1b, h);

    // 2) fused Q,K,V projections
    dim3 gqkv(DM / 256, MM / 128, 3);
    tgemm_kernel<0><<<gqkv, 256, SM_BYTES>>>(h, rwq, rwk, rwv, nullptr, nullptr,
                                             q, k, v, DM, DM);

    // 3) causal flash attention (tf32-rounded output)
    dim3 ga(TT / 128, NH, BB);
    attn_kernel<<<ga, 128>>>(q, k, v, att);

    // 4) x1 = x + att @ Wo + bo
    dim3 g1(DM / 256, MM / 128, 1);
    tgemm_kernel<1><<<g1, 256, SM_BYTES>>>(att, rwo, rwo, rwo, bo, x,
                                           x1, x1, x1, DM, DM);

    // 5) LN2 (tf32-rounded output)
    ln_kernel<<<MM, 256>>>(x1, ln2g, ln2b, h);

    // 6) mid = relu(h @ W1 + b1)  (tf32-rounded output)
    dim3 g2(DFF / 256, MM / 128, 1);
    tgemm_kernel<2><<<g2, 256, SM_BYTES>>>(h, rw1, rw1, rw1, b1, nullptr,
                                           mid, mid, mid, DM, DFF);

    // 7) out = x1 + mid @ W2 + b2
    tgemm_kernel<1><<<g1, 256, SM_BYTES>>>(mid, rw2, rw2, rw2, b2, x1,
                                           out, out, out, DFF, DM);
}

// round 9
// speedup vs baseline: 3.6939x; 1.3592x over previous
#include <cuda_runtime.h>
#include <cuda_fp16.h>
#include <math.h>
#include <stdint.h>

// Problem constants
#define BB   8
#define TT   1024
#define DM   1024
#define NH   16
#define HS   64
#define MM   (BB*TT)          // 8192 rows
#define DFF  (4*DM)           // 4096

// ---------------- scratch (device globals; no allocation allowed) ------------
__device__ __half g_h  [MM*DM];                 // LN outputs (fp16)
__device__ float  g_q  [MM*DM];
__device__ float  g_k  [MM*DM];
__device__ float  g_v  [MM*DM];
__device__ __half g_att[MM*DM];                 // attention output (fp16)
__device__ float  g_x1 [MM*DM];
__device__ __half g_mid[(size_t)MM*DFF];        // MLP mid (fp16)
// fp16 weight copies (layout unchanged: [K,N] row-major)
__device__ __half g_hwq[DM*DM];
__device__ __half g_hwk[DM*DM];
__device__ __half g_hwv[DM*DM];
__device__ __half g_hwo[DM*DM];
__device__ __half g_hw1[(size_t)DM*DFF];
__device__ __half g_hw2[(size_t)DFF*DM];

// ---------------- helpers ----------------------------------------------------
__device__ __forceinline__ uint32_t smem_u32(const void* p) {
    uint32_t a;
    asm("{ .reg .u64 t; cvta.to.shared.u64 t, %1; cvt.u32.u64 %0, t; }" : "=r"(a) : "l"(p));
    return a;
}
__device__ __forceinline__ void cp16(uint32_t dst, const void* src) {
    asm volatile("cp.async.cg.shared.global [%0], [%1], 16;" :: "r"(dst), "l"(src));
}
__device__ __forceinline__ void cp_commit() {
    asm volatile("cp.async.commit_group;" ::: "memory");
}
template<int N>
__device__ __forceinline__ void cp_wait() {
    asm volatile("cp.async.wait_group %0;" :: "n"(N) : "memory");
}
__device__ __forceinline__ void ldsm_x4(uint32_t* r, uint32_t addr) {
    asm volatile("ldmatrix.sync.aligned.m8n8.x4.shared.b16 {%0,%1,%2,%3}, [%4];"
        : "=r"(r[0]), "=r"(r[1]), "=r"(r[2]), "=r"(r[3]) : "r"(addr));
}
__device__ __forceinline__ void ldsm_x4_t(uint32_t* r, uint32_t addr) {
    asm volatile("ldmatrix.sync.aligned.m8n8.x4.trans.shared.b16 {%0,%1,%2,%3}, [%4];"
        : "=r"(r[0]), "=r"(r[1]), "=r"(r[2]), "=r"(r[3]) : "r"(addr));
}
__device__ __forceinline__ void mma_f16(float* d, const uint32_t* a, const uint32_t* b) {
    asm volatile(
        "mma.sync.aligned.m16n8k16.row.col.f32.f16.f16.f32 "
        "{%0,%1,%2,%3}, {%4,%5,%6,%7}, {%8,%9}, {%0,%1,%2,%3};"
        : "+f"(d[0]), "+f"(d[1]), "+f"(d[2]), "+f"(d[3])
        : "r"(a[0]), "r"(a[1]), "r"(a[2]), "r"(a[3]), "r"(b[0]), "r"(b[1]));
}

// smem geometry (bytes). K-chunk = 64 halves.
// A stride 144B (=9 x 16B banks, odd -> conflict-free ldmatrix rows)
// B stride 528B (=33 x 16B banks, odd -> conflict-free)
#define AS_STRIDE_B 144
#define BS_STRIDE_B 528
#define A_STAGE_B   (128 * AS_STRIDE_B)          // 18432
#define B_STAGE_B   (64  * BS_STRIDE_B)          // 33792
#define STAGE_B     (A_STAGE_B + B_STAGE_B)      // 52224
#define SM_BYTES    (3 * STAGE_B)                // 156672

// ---------------- LayerNorm (fp32 in -> fp16 out) ----------------------------
__global__ __launch_bounds__(256) void ln_kernel(
    const float* __restrict__ x, const float* __restrict__ g,
    const float* __restrict__ b, __half* __restrict__ out)
{
    const int row = blockIdx.x;
    const int tid = threadIdx.x;
    const float4* xr = (const float4*)(x + (size_t)row * DM);
    float4 v = xr[tid];
    float s  = v.x + v.y + v.z + v.w;
    float sq = v.x*v.x + v.y*v.y + v.z*v.z + v.w*v.w;
    #pragma unroll
    for (int off = 16; off; off >>= 1) {
        s  += __shfl_xor_sync(0xffffffffu, s,  off);
        sq += __shfl_xor_sync(0xffffffffu, sq, off);
    }
    __shared__ float ss[8], ssq[8];
    const int w = tid >> 5, lane = tid & 31;
    if (lane == 0) { ss[w] = s; ssq[w] = sq; }
    __syncthreads();
    float tot = 0.f, totq = 0.f;
    #pragma unroll
    for (int i = 0; i < 8; i++) { tot += ss[i]; totq += ssq[i]; }
    const float mean = tot * (1.f / DM);
    const float var  = totq * (1.f / DM) - mean * mean;
    const float inv  = rsqrtf(var + 1e-5f);
    float4 gg = ((const float4*)g)[tid];
    float4 bb = ((const float4*)b)[tid];
    __half2* orow = (__half2*)(out + (size_t)row * DM);
    orow[tid*2]   = __floats2half2_rn((v.x-mean)*inv*gg.x + bb.x, (v.y-mean)*inv*gg.y + bb.y);
    orow[tid*2+1] = __floats2half2_rn((v.z-mean)*inv*gg.z + bb.z, (v.w-mean)*inv*gg.w + bb.w);
}

// ---------------- weight fp32 -> fp16 ----------------------------------------
__global__ __launch_bounds__(256) void cvt_half_kernel(
    const float* __restrict__ src, __half* __restrict__ dst, int n4)
{
    const int i = blockIdx.x * 256 + threadIdx.x;
    if (i < n4) {
        float4 v = ((const float4*)src)[i];
        ((__half2*)dst)[2*i]   = __floats2half2_rn(v.x, v.y);
        ((__half2*)dst)[2*i+1] = __floats2half2_rn(v.z, v.w);
    }
}

// ---------------- fp16 tensor GEMM, 128x256 tile, K-chunk 64, 3-stage --------
// C = A[M x K] @ W[K x N]; A, W fp16; accumulate fp32.
// MODE 0: plain, fp32 out (z selects among 3 weight/output pairs)
// MODE 1: +bias +residual(fp32), fp32 out
// MODE 2: +bias, relu, fp16 out
template<int MODE>
__global__ __launch_bounds__(256) void tgemm_kernel(
    const __half* __restrict__ A,
    const __half* __restrict__ W0, const __half* __restrict__ W1w, const __half* __restrict__ W2w,
    const float* __restrict__ bias, const float* __restrict__ R,
    void* C0v, void* C1v, void* C2v,
    int K, int Nw)
{
    extern __shared__ __align__(128) char smc[];
    const uint32_t smBase = smem_u32(smc);

    const int tid  = threadIdx.x;
    const int wid  = tid >> 5, lane = tid & 31;
    const int warpM = wid >> 2, warpN = wid & 3;   // 2 x 4 warps, warp tile 64x64
    const int z = blockIdx.z;
    const __half* Wp = (z == 0) ? W0 : (z == 1) ? W1w : W2w;
    void* Cv = (z == 0) ? C0v : (z == 1) ? C1v : C2v;

    const int mBase = blockIdx.y * 128;
    const int nBase = blockIdx.x * 256;
    const __half* Aptr = A  + (size_t)mBase * K;
    const __half* Bptr = Wp + nBase;

    float acc[4][8][4];
    #pragma unroll
    for (int i = 0; i < 4; i++)
        #pragma unroll
        for (int j = 0; j < 8; j++)
            #pragma unroll
            for (int t = 0; t < 4; t++) acc[i][j][t] = 0.f;

    auto FILL = [&](int c) {
        const int k0 = c * 64;                       // in halves
        const uint32_t aB = smBase + (uint32_t)((c % 3) * STAGE_B);
        const uint32_t bB = aB + A_STAGE_B;
        // A: 128 rows x 8 16B-chunks = 1024 -> 4/thread
        #pragma unroll
        for (int i = 0; i < 4; i++) {
            const int idx = i * 256 + tid;
            const int r = idx >> 3, cc = idx & 7;
            cp16(aB + (uint32_t)(r * AS_STRIDE_B + cc * 16),
                 Aptr + (size_t)r * K + k0 + cc * 8);
        }
        // B: 64 rows x 32 16B-chunks = 2048 -> 8/thread
        #pragma unroll
        for (int i = 0; i < 8; i++) {
            const int idx = i * 256 + tid;
            const int r = idx >> 5, cc = idx & 31;
            cp16(bB + (uint32_t)(r * BS_STRIDE_B + cc * 16),
                 Bptr + (size_t)(k0 + r) * Nw + cc * 8);
        }
        cp_commit();
    };

    auto COMPUTE = [&](int buf) {
        const uint32_t aB = smBase + (uint32_t)(buf * STAGE_B);
        const uint32_t bB = aB + A_STAGE_B;
        // per-lane ldmatrix row addressing
        const int lr  = (lane & 7) + ((lane >> 3) & 1) * 8;   // row within 16
        const int lc8 = (lane >> 4) * 8;                      // 0 or 8 halves
        #pragma unroll
        for (int kk = 0; kk < 4; kk++) {
            uint32_t af[4][4], bf[8][2];
            #pragma unroll
            for (int mi = 0; mi < 4; mi++) {
                const int row = warpM * 64 + mi * 16 + lr;
                ldsm_x4(af[mi], aB + (uint32_t)(row * AS_STRIDE_B + (kk * 16 + lc8) * 2));
            }
            #pragma unroll
            for (int np = 0; np < 4; np++) {
                uint32_t r4[4];
                const int krow = kk * 16 + lr;
                const int col  = warpN * 64 + np * 16 + lc8;
                ldsm_x4_t(r4, bB + (uint32_t)(krow * BS_STRIDE_B + col * 2));
                bf[np*2][0]   = r4[0]; bf[np*2][1]   = r4[1];
                bf[np*2+1][0] = r4[2]; bf[np*2+1][1] = r4[3];
            }
            #pragma unroll
            for (int mi = 0; mi < 4; mi++)
                #pragma unroll
                for (int ni = 0; ni < 8; ni++)
                    mma_f16(acc[mi][ni], af[mi], bf[ni]);
        }
    };

    const int nch = K / 64;
    FILL(0);
    FILL(1);
    for (int c = 0; c < nch; c++) {
        if (c == nch - 1) cp_wait<0>(); else cp_wait<1>();
        __syncthreads();
        if (c + 2 < nch) FILL(c + 2);
        COMPUTE(c % 3);
        __syncthreads();
    }

    // ---- epilogue ----
    #pragma unroll
    for (int mi = 0; mi < 4; mi++) {
        #pragma unroll
        for (int ni = 0; ni < 8; ni++) {
            const int gr = mBase + warpM * 64 + mi * 16 + (lane >> 2);
            const int gc = nBase + warpN * 64 + ni * 8 + (lane & 3) * 2;
            float v0 = acc[mi][ni][0], v1 = acc[mi][ni][1];
            float v2 = acc[mi][ni][2], v3 = acc[mi][ni][3];
            if (MODE != 0) {
                const float b0 = bias[gc], b1 = bias[gc + 1];
                v0 += b0; v1 += b1; v2 += b0; v3 += b1;
            }
            if (MODE == 1) {
                const float* r0p = R + (size_t)gr * Nw + gc;
                const float* r1p = R + (size_t)(gr + 8) * Nw + gc;
                v0 += r0p[0]; v1 += r0p[1]; v2 += r1p[0]; v3 += r1p[1];
            }
            if constexpr (MODE == 2) {
                __half* C = (__half*)Cv;
                v0 = fmaxf(v0, 0.f); v1 = fmaxf(v1, 0.f);
                v2 = fmaxf(v2, 0.f); v3 = fmaxf(v3, 0.f);
                *(__half2*)(C + (size_t)gr * Nw + gc)       = __floats2half2_rn(v0, v1);
                *(__half2*)(C + (size_t)(gr + 8) * Nw + gc) = __floats2half2_rn(v2, v3);
            } else {
                float* C = (float*)Cv;
                *(float2*)(C + (size_t)gr * Nw + gc)       = make_float2(v0, v1);
                *(float2*)(C + (size_t)(gr + 8) * Nw + gc) = make_float2(v2, v3);
            }
        }
    }
}

// ---------------- Flash attention (causal, scale = 1/sqrt(D) = 1/32) --------
// fp32 q/k/v in, fp16 out (consumed as GEMM A operand)
__global__ __launch_bounds__(128, 1) void attn_kernel(
    const float* __restrict__ Q, const float* __restrict__ K,
    const float* __restrict__ V, __half* __restrict__ O)
{
    __shared__ float Ks[32][64];
    __shared__ float Vs[32][64];
    __shared__ float Ps[128][33];

    const int tid = threadIdx.x;
    const int qt = blockIdx.x, hh = blockIdx.y, bb = blockIdx.z;
    const int qi = qt * 128 + tid;
    const size_t base = (size_t)bb * TT * DM + (size_t)hh * HS;

    const float4* qr = (const float4*)(Q + base + (size_t)qi * DM);
    float4 q4[16], o4[16];
    #pragma unroll
    for (int i = 0; i < 16; i++) { q4[i] = qr[i]; o4[i] = make_float4(0.f, 0.f, 0.f, 0.f); }

    float m = -1e30f, l = 0.f;
    const int nkt = qt * 4 + 4;

    for (int kt = 0; kt < nkt; kt++) {
        __syncthreads();
        #pragma unroll
        for (int i = 0; i < 4; i++) {
            const int slot = i * 128 + tid;
            const int r = slot >> 4, c = slot & 15;
            const size_t gidx = base + (size_t)(kt * 32 + r) * DM + (size_t)c * 4;
            ((float4*)Ks)[slot] = *(const float4*)(K + gidx);
            ((float4*)Vs)[slot] = *(const float4*)(V + gidx);
        }
        __syncthreads();

        float tmax = -1e30f;
        #pragma unroll 4
        for (int j = 0; j < 32; j++) {
            const float4* kr = (const float4*)&Ks[j][0];
            float s = 0.f;
            #pragma unroll
            for (int d = 0; d < 16; d++) {
                float4 kk = kr[d];
                s += q4[d].x * kk.x + q4[d].y * kk.y + q4[d].z * kk.z + q4[d].w * kk.w;
            }
            s *= 0.03125f;
            if (kt * 32 + j > qi) s = -1e30f;
            Ps[tid][j] = s;
            tmax = fmaxf(tmax, s);
        }

        const float mnew = fmaxf(m, tmax);
        const float corr = __expf(m - mnew);
        l *= corr;
        #pragma unroll
        for (int i = 0; i < 16; i++) {
            o4[i].x *= corr; o4[i].y *= corr; o4[i].z *= corr; o4[i].w *= corr;
        }
        #pragma unroll 4
        for (int j = 0; j < 32; j++) {
            const float p = __expf(Ps[tid][j] - mnew);
            Ps[tid][j] = p;
            l += p;
        }
        m = mnew;

        #pragma unroll 2
        for (int j = 0; j < 32; j++) {
            const float p = Ps[tid][j];
            const float4* vr = (const float4*)&Vs[j][0];
            #pragma unroll
            for (int d = 0; d < 16; d++) {
                float4 vv = vr[d];
                o4[d].x += p * vv.x; o4[d].y += p * vv.y;
                o4[d].z += p * vv.z; o4[d].w += p * vv.w;
            }
        }
    }

    const float inv = 1.f / l;
    __half2* orow = (__half2*)(O + base + (size_t)qi * DM);
    #pragma unroll
    for (int i = 0; i < 16; i++) {
        orow[i*2]   = __floats2half2_rn(o4[i].x * inv, o4[i].y * inv);
        orow[i*2+1] = __floats2half2_rn(o4[i].z * inv, o4[i].w * inv);
    }
}

// ---------------- launch ----------------------------------------------------
extern "C" void kernel_launch(void* const* d_in, const int* in_sizes, int n_in,
                              void* d_out, int out_size)
{
    const float* x    = (const float*)d_in[0];
    const float* Wq   = (const float*)d_in[1];
    const float* Wk   = (const float*)d_in[2];
    const float* Wv   = (const float*)d_in[3];
    const float* Wo   = (const float*)d_in[4];
    const float* bo   = (const float*)d_in[5];
    const float* W1   = (const float*)d_in[6];
    const float* b1   = (const float*)d_in[7];
    const float* W2   = (const float*)d_in[8];
    const float* b2   = (const float*)d_in[9];
    const float* ln1g = (const float*)d_in[10];
    const float* ln1b = (const float*)d_in[11];
    const float* ln2g = (const float*)d_in[12];
    const float* ln2b = (const float*)d_in[13];
    float* out = (float*)d_out;

    __half *h, *att, *mid, *hwq, *hwk, *hwv, *hwo, *hw1, *hw2;
    float *q, *k, *v, *x1;
    cudaGetSymbolAddress((void**)&h,   g_h);
    cudaGetSymbolAddress((void**)&q,   g_q);
    cudaGetSymbolAddress((void**)&k,   g_k);
    cudaGetSymbolAddress((void**)&v,   g_v);
    cudaGetSymbolAddress((void**)&att, g_att);
    cudaGetSymbolAddress((void**)&x1,  g_x1);
    cudaGetSymbolAddress((void**)&mid, g_mid);
    cudaGetSymbolAddress((void**)&hwq, g_hwq);
    cudaGetSymbolAddress((void**)&hwk, g_hwk);
    cudaGetSymbolAddress((void**)&hwv, g_hwv);
    cudaGetSymbolAddress((void**)&hwo, g_hwo);
    cudaGetSymbolAddress((void**)&hw1, g_hw1);
    cudaGetSymbolAddress((void**)&hw2, g_hw2);

    cudaFuncSetAttribute(tgemm_kernel<0>, cudaFuncAttributeMaxDynamicSharedMemorySize, SM_BYTES);
    cudaFuncSetAttribute(tgemm_kernel<1>, cudaFuncAttributeMaxDynamicSharedMemorySize, SM_BYTES);
    cudaFuncSetAttribute(tgemm_kernel<2>, cudaFuncAttributeMaxDynamicSharedMemorySize, SM_BYTES);

    // 0) convert weights to fp16 once per call
    const int n4d = DM * DM / 4, n4f = DM * DFF / 4;
    cvt_half_kernel<<<(n4d + 255) / 256, 256>>>(Wq, hwq, n4d);
    cvt_half_kernel<<<(n4d + 255) / 256, 256>>>(Wk, hwk, n4d);
    cvt_half_kernel<<<(n4d + 255) / 256, 256>>>(Wv, hwv, n4d);
    cvt_half_kernel<<<(n4d + 255) / 256, 256>>>(Wo, hwo, n4d);
    cvt_half_kernel<<<(n4f + 255) / 256, 256>>>(W1, hw1, n4f);
    cvt_half_kernel<<<(n4f + 255) / 256, 256>>>(W2, hw2, n4f);

    // 1) LN1 -> fp16
    ln_kernel<<<MM, 256>>>(x, ln1g, ln1b, h);

    // 2) fused Q,K,V projections (fp32 outputs for fp32 attention)
    dim3 gqkv(DM / 256, MM / 128, 3);
    tgemm_kernel<0><<<gqkv, 256, SM_BYTES>>>(h, hwq, hwk, hwv, nullptr, nullptr,
                                             q, k, v, DM, DM);

    // 3) causal flash attention -> fp16 att
    dim3 ga(TT / 128, NH, BB);
    attn_kernel<<<ga, 128>>>(q, k, v, att);

    // 4) x1 = x + att @ Wo + bo
    dim3 g1(DM / 256, MM / 128, 1);
    tgemm_kernel<1><<<g1, 256, SM_BYTES>>>(att, hwo, hwo, hwo, bo, x,
                                           x1, x1, x1, DM, DM);

    // 5) LN2 -> fp16
    ln_kernel<<<MM, 256>>>(x1, ln2g, ln2b, h);

    // 6) mid = relu(h @ W1 + b1) -> fp16
    dim3 g2(DFF / 256, MM / 128, 1);
    tgemm_kernel<2><<<g2, 256, SM_BYTES>>>(h, hw1, hw1, hw1, b1, nullptr,
                                           mid, mid, mid, DM, DFF);

    // 7) out = x1 + mid @ W2 + b2
    tgemm_kernel<1><<<g1, 256, SM_BYTES>>>(mid, hw2, hw2, hw2, b2, x1,
                                           out, out, out, DFF, DM);
}

// round 11
// speedup vs baseline: 6.9323x; 1.8767x over previous
#include <cuda_runtime.h>
#include <cuda_fp16.h>
#include <math.h>
#include <stdint.h>

// Problem constants
#define BB   8
#define TT   1024
#define DM   1024
#define NH   16
#define HS   64
#define MM   (BB*TT)          // 8192 rows
#define DFF  (4*DM)           // 4096

// ---------------- scratch (device globals; no allocation allowed) ------------
__device__ __half g_h  [MM*DM];                 // LN outputs (fp16)
__device__ __half g_q  [MM*DM];
__device__ __half g_k  [MM*DM];
__device__ __half g_v  [MM*DM];
__device__ __half g_att[MM*DM];                 // attention output (fp16)
__device__ float  g_x1 [MM*DM];
__device__ __half g_mid[(size_t)MM*DFF];        // MLP mid (fp16)
// fp16 weight copies (layout unchanged: [K,N] row-major)
__device__ __half g_hwq[DM*DM];
__device__ __half g_hwk[DM*DM];
__device__ __half g_hwv[DM*DM];
__device__ __half g_hwo[DM*DM];
__device__ __half g_hw1[(size_t)DM*DFF];
__device__ __half g_hw2[(size_t)DFF*DM];

// ---------------- helpers ----------------------------------------------------
__device__ __forceinline__ uint32_t smem_u32(const void* p) {
    uint32_t a;
    asm("{ .reg .u64 t; cvta.to.shared.u64 t, %1; cvt.u32.u64 %0, t; }" : "=r"(a) : "l"(p));
    return a;
}
__device__ __forceinline__ void cp16(uint32_t dst, const void* src) {
    asm volatile("cp.async.cg.shared.global [%0], [%1], 16;" :: "r"(dst), "l"(src));
}
__device__ __forceinline__ void cp_commit() {
    asm volatile("cp.async.commit_group;" ::: "memory");
}
template<int N>
__device__ __forceinline__ void cp_wait() {
    asm volatile("cp.async.wait_group %0;" :: "n"(N) : "memory");
}
__device__ __forceinline__ void ldsm_x4(uint32_t* r, uint32_t addr) {
    asm volatile("ldmatrix.sync.aligned.m8n8.x4.shared.b16 {%0,%1,%2,%3}, [%4];"
        : "=r"(r[0]), "=r"(r[1]), "=r"(r[2]), "=r"(r[3]) : "r"(addr));
}
__device__ __forceinline__ void ldsm_x4_t(uint32_t* r, uint32_t addr) {
    asm volatile("ldmatrix.sync.aligned.m8n8.x4.trans.shared.b16 {%0,%1,%2,%3}, [%4];"
        : "=r"(r[0]), "=r"(r[1]), "=r"(r[2]), "=r"(r[3]) : "r"(addr));
}
__device__ __forceinline__ void mma_f16(float* d, const uint32_t* a, const uint32_t* b) {
    asm volatile(
        "mma.sync.aligned.m16n8k16.row.col.f32.f16.f16.f32 "
        "{%0,%1,%2,%3}, {%4,%5,%6,%7}, {%8,%9}, {%0,%1,%2,%3};"
        : "+f"(d[0]), "+f"(d[1]), "+f"(d[2]), "+f"(d[3])
        : "r"(a[0]), "r"(a[1]), "r"(a[2]), "r"(a[3]), "r"(b[0]), "r"(b[1]));
}

// GEMM smem geometry (bytes). K-chunk = 64 halves.
#define AS_STRIDE_B 144
#define BS_STRIDE_B 528
#define A_STAGE_B   (128 * AS_STRIDE_B)
#define B_STAGE_B   (64  * BS_STRIDE_B)
#define STAGE_B     (A_STAGE_B + B_STAGE_B)
#define SM_BYTES    (3 * STAGE_B)               // 156672

// ---------------- LayerNorm (fp32 in -> fp16 out) ----------------------------
__global__ __launch_bounds__(256) void ln_kernel(
    const float* __restrict__ x, const float* __restrict__ g,
    const float* __restrict__ b, __half* __restrict__ out)
{
    const int row = blockIdx.x;
    const int tid = threadIdx.x;
    const float4* xr = (const float4*)(x + (size_t)row * DM);
    float4 v = xr[tid];
    float s  = v.x + v.y + v.z + v.w;
    float sq = v.x*v.x + v.y*v.y + v.z*v.z + v.w*v.w;
    #pragma unroll
    for (int off = 16; off; off >>= 1) {
        s  += __shfl_xor_sync(0xffffffffu, s,  off);
        sq += __shfl_xor_sync(0xffffffffu, sq, off);
    }
    __shared__ float ss[8], ssq[8];
    const int w = tid >> 5, lane = tid & 31;
    if (lane == 0) { ss[w] = s; ssq[w] = sq; }
    __syncthreads();
    float tot = 0.f, totq = 0.f;
    #pragma unroll
    for (int i = 0; i < 8; i++) { tot += ss[i]; totq += ssq[i]; }
    const float mean = tot * (1.f / DM);
    const float var  = totq * (1.f / DM) - mean * mean;
    const float inv  = rsqrtf(var + 1e-5f);
    float4 gg = ((const float4*)g)[tid];
    float4 bb = ((const float4*)b)[tid];
    __half2* orow = (__half2*)(out + (size_t)row * DM);
    orow[tid*2]   = __floats2half2_rn((v.x-mean)*inv*gg.x + bb.x, (v.y-mean)*inv*gg.y + bb.y);
    orow[tid*2+1] = __floats2half2_rn((v.z-mean)*inv*gg.z + bb.z, (v.w-mean)*inv*gg.w + bb.w);
}

// ---------------- weight fp32 -> fp16 ----------------------------------------
__global__ __launch_bounds__(256) void cvt_half_kernel(
    const float* __restrict__ src, __half* __restrict__ dst, int n4)
{
    const int i = blockIdx.x * 256 + threadIdx.x;
    if (i < n4) {
        float4 v = ((const float4*)src)[i];
        ((__half2*)dst)[2*i]   = __floats2half2_rn(v.x, v.y);
        ((__half2*)dst)[2*i+1] = __floats2half2_rn(v.z, v.w);
    }
}

// ---------------- fp16 tensor GEMM, 128x256 tile, K-chunk 64, 3-stage --------
// MODE 0: plain, fp16 out (z selects among 3 weight/output pairs)
// MODE 1: +bias +residual(fp32), fp32 out
// MODE 2: +bias, relu, fp16 out
template<int MODE>
__global__ __launch_bounds__(256) void tgemm_kernel(
    const __half* __restrict__ A,
    const __half* __restrict__ W0, const __half* __restrict__ W1w, const __half* __restrict__ W2w,
    const float* __restrict__ bias, const float* __restrict__ R,
    void* C0v, void* C1v, void* C2v,
    int K, int Nw)
{
    extern __shared__ __align__(128) char smc[];
    const uint32_t smBase = smem_u32(smc);

    const int tid  = threadIdx.x;
    const int wid  = tid >> 5, lane = tid & 31;
    const int warpM = wid >> 2, warpN = wid & 3;
    const int z = blockIdx.z;
    const __half* Wp = (z == 0) ? W0 : (z == 1) ? W1w : W2w;
    void* Cv = (z == 0) ? C0v : (z == 1) ? C1v : C2v;

    const int mBase = blockIdx.y * 128;
    const int nBase = blockIdx.x * 256;
    const __half* Aptr = A  + (size_t)mBase * K;
    const __half* Bptr = Wp + nBase;

    float acc[4][8][4];
    #pragma unroll
    for (int i = 0; i < 4; i++)
        #pragma unroll
        for (int j = 0; j < 8; j++)
            #pragma unroll
            for (int t = 0; t < 4; t++) acc[i][j][t] = 0.f;

    auto FILL = [&](int c) {
        const int k0 = c * 64;
        const uint32_t aB = smBase + (uint32_t)((c % 3) * STAGE_B);
        const uint32_t bB = aB + A_STAGE_B;
        #pragma unroll
        for (int i = 0; i < 4; i++) {
            const int idx = i * 256 + tid;
            const int r = idx >> 3, cc = idx & 7;
            cp16(aB + (uint32_t)(r * AS_STRIDE_B + cc * 16),
                 Aptr + (size_t)r * K + k0 + cc * 8);
        }
        #pragma unroll
        for (int i = 0; i < 8; i++) {
            const int idx = i * 256 + tid;
            const int r = idx >> 5, cc = idx & 31;
            cp16(bB + (uint32_t)(r * BS_STRIDE_B + cc * 16),
                 Bptr + (size_t)(k0 + r) * Nw + cc * 8);
        }
        cp_commit();
    };

    auto COMPUTE = [&](int buf) {
        const uint32_t aB = smBase + (uint32_t)(buf * STAGE_B);
        const uint32_t bB = aB + A_STAGE_B;
        const int lr  = (lane & 7) + ((lane >> 3) & 1) * 8;
        const int lc8 = (lane >> 4) * 8;
        #pragma unroll
        for (int kk = 0; kk < 4; kk++) {
            uint32_t af[4][4], bf[8][2];
            #pragma unroll
            for (int mi = 0; mi < 4; mi++) {
                const int row = warpM * 64 + mi * 16 + lr;
                ldsm_x4(af[mi], aB + (uint32_t)(row * AS_STRIDE_B + (kk * 16 + lc8) * 2));
            }
            #pragma unroll
            for (int np = 0; np < 4; np++) {
                uint32_t r4[4];
                const int krow = kk * 16 + lr;
                const int col  = warpN * 64 + np * 16 + lc8;
                ldsm_x4_t(r4, bB + (uint32_t)(krow * BS_STRIDE_B + col * 2));
                bf[np*2][0]   = r4[0]; bf[np*2][1]   = r4[1];
                bf[np*2+1][0] = r4[2]; bf[np*2+1][1] = r4[3];
            }
            #pragma unroll
            for (int mi = 0; mi < 4; mi++)
                #pragma unroll
                for (int ni = 0; ni < 8; ni++)
                    mma_f16(acc[mi][ni], af[mi], bf[ni]);
        }
    };

    const int nch = K / 64;
    FILL(0);
    FILL(1);
    for (int c = 0; c < nch; c++) {
        if (c == nch - 1) cp_wait<0>(); else cp_wait<1>();
        __syncthreads();
        if (c + 2 < nch) FILL(c + 2);
        COMPUTE(c % 3);
        __syncthreads();
    }

    #pragma unroll
    for (int mi = 0; mi < 4; mi++) {
        #pragma unroll
        for (int ni = 0; ni < 8; ni++) {
            const int gr = mBase + warpM * 64 + mi * 16 + (lane >> 2);
            const int gc = nBase + warpN * 64 + ni * 8 + (lane & 3) * 2;
            float v0 = acc[mi][ni][0], v1 = acc[mi][ni][1];
            float v2 = acc[mi][ni][2], v3 = acc[mi][ni][3];
            if (MODE != 0) {
                const float b0 = bias[gc], b1 = bias[gc + 1];
                v0 += b0; v1 += b1; v2 += b0; v3 += b1;
            }
            if (MODE == 1) {
                const float* r0p = R + (size_t)gr * Nw + gc;
                const float* r1p = R + (size_t)(gr + 8) * Nw + gc;
                v0 += r0p[0]; v1 += r0p[1]; v2 += r1p[0]; v3 += r1p[1];
            }
            if constexpr (MODE != 1) {
                __half* C = (__half*)Cv;
                if (MODE == 2) {
                    v0 = fmaxf(v0, 0.f); v1 = fmaxf(v1, 0.f);
                    v2 = fmaxf(v2, 0.f); v3 = fmaxf(v3, 0.f);
                }
                *(__half2*)(C + (size_t)gr * Nw + gc)       = __floats2half2_rn(v0, v1);
                *(__half2*)(C + (size_t)(gr + 8) * Nw + gc) = __floats2half2_rn(v2, v3);
            } else {
                float* C = (float*)Cv;
                *(float2*)(C + (size_t)gr * Nw + gc)       = make_float2(v0, v1);
                *(float2*)(C + (size_t)(gr + 8) * Nw + gc) = make_float2(v2, v3);
            }
        }
    }
}

// ---------------- Tensor-core flash attention (causal, scale 1/32) -----------
#define KS_STRIDE 144                 // bytes per row (64 halves + 8 pad)
#define Q_SMEM_B  (128 * KS_STRIDE)   // 18432
#define KV_TILE_B (64 * KS_STRIDE)    // 9216
#define ATT_SMEM  (Q_SMEM_B + 4 * KV_TILE_B)   // 55296

__global__ __launch_bounds__(128) void attn_kernel(
    const __half* __restrict__ Q, const __half* __restrict__ K,
    const __half* __restrict__ V, __half* __restrict__ O)
{
    extern __shared__ __align__(128) char smc[];
    const uint32_t smBase = smem_u32(smc);

    const int tid = threadIdx.x;
    const int wid = tid >> 5, lane = tid & 31;
    const int qt = blockIdx.x, hh = blockIdx.y, bb = blockIdx.z;
    const int qb = qt * 128;
    const size_t base = (size_t)bb * TT * DM + (size_t)hh * HS;

    const int lr  = (lane & 7) + ((lane >> 3) & 1) * 8;
    const int lc8 = (lane >> 4) * 8;

    // ---- fill Q (128 rows); committed together with KV tile 0 as group 0 ----
    #pragma unroll
    for (int i = 0; i < 8; i++) {
        const int idx = i * 128 + tid;
        const int r = idx >> 3, c = idx & 7;
        cp16(smBase + (uint32_t)(r * KS_STRIDE + c * 16),
             Q + base + (size_t)(qb + r) * DM + c * 8);
    }
    auto FILLKV = [&](int kt) {
        const int s = kt & 1;
        const uint32_t kB = smBase + Q_SMEM_B + (uint32_t)(s * KV_TILE_B);
        const uint32_t vB = smBase + Q_SMEM_B + (uint32_t)((2 + s) * KV_TILE_B);
        #pragma unroll
        for (int i = 0; i < 4; i++) {
            const int idx = i * 128 + tid;
            const int r = idx >> 3, c = idx & 7;
            const size_t g = base + (size_t)(kt * 64 + r) * DM + c * 8;
            cp16(kB + (uint32_t)(r * KS_STRIDE + c * 16), K + g);
            cp16(vB + (uint32_t)(r * KS_STRIDE + c * 16), V + g);
        }
        cp_commit();
    };
    const int ntiles = 2 * qt + 2;
    FILLKV(0);              // group 0: Q + KV0
    FILLKV(1);              // group 1: KV1

    uint32_t qa[2][4][4];
    float oacc[2][8][4];
    float mrow[2][2], lrow[2][2];
    #pragma unroll
    for (int mi = 0; mi < 2; mi++) {
        mrow[mi][0] = mrow[mi][1] = -1e30f;
        lrow[mi][0] = lrow[mi][1] = 0.f;
        #pragma unroll
        for (int ni = 0; ni < 8; ni++)
            #pragma unroll
            for (int t = 0; t < 4; t++) oacc[mi][ni][t] = 0.f;
    }

    for (int kt = 0; kt < ntiles; kt++) {
        if (kt + 1 < ntiles) cp_wait<1>(); else cp_wait<0>();
        __syncthreads();
        if (kt == 0) {
            #pragma unroll
            for (int mi = 0; mi < 2; mi++)
                #pragma unroll
                for (int kk = 0; kk < 4; kk++) {
                    const int row = wid * 32 + mi * 16 + lr;
                    ldsm_x4(qa[mi][kk],
                            smBase + (uint32_t)(row * KS_STRIDE + (kk * 16 + lc8) * 2));
                }
        }
        const int s = kt & 1;
        const uint32_t kB = smBase + Q_SMEM_B + (uint32_t)(s * KV_TILE_B);
        const uint32_t vB = smBase + Q_SMEM_B + (uint32_t)((2 + s) * KV_TILE_B);

        // ---- S = Q @ K^T ----
        float sacc[2][8][4];
        #pragma unroll
        for (int mi = 0; mi < 2; mi++)
            #pragma unroll
            for (int ni = 0; ni < 8; ni++)
                #pragma unroll
                for (int t = 0; t < 4; t++) sacc[mi][ni][t] = 0.f;
        #pragma unroll
        for (int kk = 0; kk < 4; kk++) {
            uint32_t kb[8][2];
            #pragma unroll
            for (int ng = 0; ng < 4; ng++) {
                uint32_t r4[4];
                ldsm_x4(r4, kB + (uint32_t)((ng * 16 + lr) * KS_STRIDE + (kk * 16 + lc8) * 2));
                kb[ng*2][0]   = r4[0]; kb[ng*2][1]   = r4[2];
                kb[ng*2+1][0] = r4[1]; kb[ng*2+1][1] = r4[3];
            }
            #pragma unroll
            for (int mi = 0; mi < 2; mi++)
                #pragma unroll
                for (int ni = 0; ni < 8; ni++)
                    mma_f16(sacc[mi][ni], qa[mi][kk], kb[ni]);
        }

        // ---- online softmax in fragments ----
        const bool doMask = (kt >= 2 * qt);
        uint32_t pa[2][4][4];
        #pragma unroll
        for (int mi = 0; mi < 2; mi++) {
            const int row0 = qb + wid * 32 + mi * 16 + (lane >> 2);
            const int row1 = row0 + 8;
            float mx0 = -1e30f, mx1 = -1e30f;
            #pragma unroll
            for (int ni = 0; ni < 8; ni++) {
                const int c0 = kt * 64 + ni * 8 + (lane & 3) * 2;
                float s0 = sacc[mi][ni][0] * 0.03125f;
                float s1 = sacc[mi][ni][1] * 0.03125f;
                float s2 = sacc[mi][ni][2] * 0.03125f;
                float s3 = sacc[mi][ni][3] * 0.03125f;
                if (doMask) {
                    if (c0     > row0) s0 = -1e30f;
                    if (c0 + 1 > row0) s1 = -1e30f;
                    if (c0     > row1) s2 = -1e30f;
                    if (c0 + 1 > row1) s3 = -1e30f;
                }
                sacc[mi][ni][0] = s0; sacc[mi][ni][1] = s1;
                sacc[mi][ni][2] = s2; sacc[mi][ni][3] = s3;
                mx0 = fmaxf(mx0, fmaxf(s0, s1));
                mx1 = fmaxf(mx1, fmaxf(s2, s3));
            }
            #pragma unroll
            for (int off = 1; off <= 2; off <<= 1) {
                mx0 = fmaxf(mx0, __shfl_xor_sync(0xffffffffu, mx0, off));
                mx1 = fmaxf(mx1, __shfl_xor_sync(0xffffffffu, mx1, off));
            }
            const float mn0 = fmaxf(mrow[mi][0], mx0);
            const float mn1 = fmaxf(mrow[mi][1], mx1);
            const float cor0 = __expf(mrow[mi][0] - mn0);
            const float cor1 = __expf(mrow[mi][1] - mn1);
            mrow[mi][0] = mn0; mrow[mi][1] = mn1;
            float sum0 = 0.f, sum1 = 0.f;
            float p[8][4];
            #pragma unroll
            for (int ni = 0; ni < 8; ni++) {
                p[ni][0] = __expf(sacc[mi][ni][0] - mn0);
                p[ni][1] = __expf(sacc[mi][ni][1] - mn0);
                p[ni][2] = __expf(sacc[mi][ni][2] - mn1);
                p[ni][3] = __expf(sacc[mi][ni][3] - mn1);
                sum0 += p[ni][0] + p[ni][1];
                sum1 += p[ni][2] + p[ni][3];
            }
            lrow[mi][0] = lrow[mi][0] * cor0 + sum0;
            lrow[mi][1] = lrow[mi][1] * cor1 + sum1;
            #pragma unroll
            for (int ni = 0; ni < 8; ni++) {
                oacc[mi][ni][0] *= cor0; oacc[mi][ni][1] *= cor0;
                oacc[mi][ni][2] *= cor1; oacc[mi][ni][3] *= cor1;
            }
            #pragma unroll
            for (int jk = 0; jk < 4; jk++) {
                __half2 h0 = __floats2half2_rn(p[2*jk][0],   p[2*jk][1]);
                __half2 h1 = __floats2half2_rn(p[2*jk][2],   p[2*jk][3]);
                __half2 h2 = __floats2half2_rn(p[2*jk+1][0], p[2*jk+1][1]);
                __half2 h3 = __floats2half2_rn(p[2*jk+1][2], p[2*jk+1][3]);
                pa[mi][jk][0] = *(uint32_t*)&h0;
                pa[mi][jk][1] = *(uint32_t*)&h1;
                pa[mi][jk][2] = *(uint32_t*)&h2;
                pa[mi][jk][3] = *(uint32_t*)&h3;
            }
        }

        // ---- O += P @ V ----
        #pragma unroll
        for (int jk = 0; jk < 4; jk++) {
            uint32_t vb[8][2];
            #pragma unroll
            for (int ng = 0; ng < 4; ng++) {
                uint32_t r4[4];
                ldsm_x4_t(r4, vB + (uint32_t)((jk * 16 + lr) * KS_STRIDE + (ng * 16 + lc8) * 2));
                vb[ng*2][0]   = r4[0]; vb[ng*2][1]   = r4[1];
                vb[ng*2+1][0] = r4[2]; vb[ng*2+1][1] = r4[3];
            }
            #pragma unroll
            for (int mi = 0; mi < 2; mi++)
                #pragma unroll
                for (int ni = 0; ni < 8; ni++)
                    mma_f16(oacc[mi][ni], pa[mi][jk], vb[ni]);
        }

        __syncthreads();
        if (kt + 2 < ntiles) FILLKV(kt + 2);
    }

    // ---- epilogue: normalize and store fp16 ----
    #pragma unroll
    for (int mi = 0; mi < 2; mi++) {
        float l0 = lrow[mi][0], l1 = lrow[mi][1];
        #pragma unroll
        for (int off = 1; off <= 2; off <<= 1) {
            l0 += __shfl_xor_sync(0xffffffffu, l0, off);
            l1 += __shfl_xor_sync(0xffffffffu, l1, off);
        }
        const float inv0 = 1.f / l0, inv1 = 1.f / l1;
        const int gr0 = qb + wid * 32 + mi * 16 + (lane >> 2);
        #pragma unroll
        for (int ni = 0; ni < 8; ni++) {
            const int gc = ni * 8 + (lane & 3) * 2;
            *(__half2*)(O + base + (size_t)gr0 * DM + gc) =
                __floats2half2_rn(oacc[mi][ni][0] * inv0, oacc[mi][ni][1] * inv0);
            *(__half2*)(O + base + (size_t)(gr0 + 8) * DM + gc) =
                __floats2half2_rn(oacc[mi][ni][2] * inv1, oacc[mi][ni][3] * inv1);
        }
    }
}

// ---------------- launch ----------------------------------------------------
extern "C" void kernel_launch(void* const* d_in, const int* in_sizes, int n_in,
                              void* d_out, int out_size)
{
    const float* x    = (const float*)d_in[0];
    const float* Wq   = (const float*)d_in[1];
    const float* Wk   = (const float*)d_in[2];
    const float* Wv   = (const float*)d_in[3];
    const float* Wo   = (const float*)d_in[4];
    const float* bo   = (const float*)d_in[5];
    const float* W1   = (const float*)d_in[6];
    const float* b1   = (const float*)d_in[7];
    const float* W2   = (const float*)d_in[8];
    const float* b2   = (const float*)d_in[9];
    const float* ln1g = (const float*)d_in[10];
    const float* ln1b = (const float*)d_in[11];
    const float* ln2g = (const float*)d_in[12];
    const float* ln2b = (const float*)d_in[13];
    float* out = (float*)d_out;

    __half *h, *q, *k, *v, *att, *mid, *hwq, *hwk, *hwv, *hwo, *hw1, *hw2;
    float *x1;
    cudaGetSymbolAddress((void**)&h,   g_h);
    cudaGetSymbolAddress((void**)&q,   g_q);
    cudaGetSymbolAddress((void**)&k,   g_k);
    cudaGetSymbolAddress((void**)&v,   g_v);
    cudaGetSymbolAddress((void**)&att, g_att);
    cudaGetSymbolAddress((void**)&x1,  g_x1);
    cudaGetSymbolAddress((void**)&mid, g_mid);
    cudaGetSymbolAddress((void**)&hwq, g_hwq);
    cudaGetSymbolAddress((void**)&hwk, g_hwk);
    cudaGetSymbolAddress((void**)&hwv, g_hwv);
    cudaGetSymbolAddress((void**)&hwo, g_hwo);
    cudaGetSymbolAddress((void**)&hw1, g_hw1);
    cudaGetSymbolAddress((void**)&hw2, g_hw2);

    cudaFuncSetAttribute(tgemm_kernel<0>, cudaFuncAttributeMaxDynamicSharedMemorySize, SM_BYTES);
    cudaFuncSetAttribute(tgemm_kernel<1>, cudaFuncAttributeMaxDynamicSharedMemorySize, SM_BYTES);
    cudaFuncSetAttribute(tgemm_kernel<2>, cudaFuncAttributeMaxDynamicSharedMemorySize, SM_BYTES);
    cudaFuncSetAttribute(attn_kernel,     cudaFuncAttributeMaxDynamicSharedMemorySize, ATT_SMEM);

    // 0) convert weights to fp16
    const int n4d = DM * DM / 4, n4f = DM * DFF / 4;
    cvt_half_kernel<<<(n4d + 255) / 256, 256>>>(Wq, hwq, n4d);
    cvt_half_kernel<<<(n4d + 255) / 256, 256>>>(Wk, hwk, n4d);
    cvt_half_kernel<<<(n4d + 255) / 256, 256>>>(Wv, hwv, n4d);
    cvt_half_kernel<<<(n4d + 255) / 256, 256>>>(Wo, hwo, n4d);
    cvt_half_kernel<<<(n4f + 255) / 256, 256>>>(W1, hw1, n4f);
    cvt_half_kernel<<<(n4f + 255) / 256, 256>>>(W2, hw2, n4f);

    // 1) LN1 -> fp16
    ln_kernel<<<MM, 256>>>(x, ln1g, ln1b, h);

    // 2) fused Q,K,V projections -> fp16
    dim3 gqkv(DM / 256, MM / 128, 3);
    tgemm_kernel<0><<<gqkv, 256, SM_BYTES>>>(h, hwq, hwk, hwv, nullptr, nullptr,
                                             q, k, v, DM, DM);

    // 3) tensor-core causal flash attention -> fp16
    dim3 ga(TT / 128, NH, BB);
    attn_kernel<<<ga, 128, ATT_SMEM>>>(q, k, v, att);

    // 4) x1 = x + att @ Wo + bo  (fp32 out)
    dim3 g1(DM / 256, MM / 128, 1);
    tgemm_kernel<1><<<g1, 256, SM_BYTES>>>(att, hwo, hwo, hwo, bo, x,
                                           x1, x1, x1, DM, DM);

    // 5) LN2 -> fp16
    ln_kernel<<<MM, 256>>>(x1, ln2g, ln2b, h);

    // 6) mid = relu(h @ W1 + b1) -> fp16
    dim3 g2(DFF / 256, MM / 128, 1);
    tgemm_kernel<2><<<g2, 256, SM_BYTES>>>(h, hw1, hw1, hw1, b1, nullptr,
                                           mid, mid, mid, DM, DFF);

    // 7) out = x1 + mid @ W2 + b2  (fp32 out)
    tgemm_kernel<1><<<g1, 256, SM_BYTES>>>(mid, hw2, hw2, hw2, b2, x1,
                                           out, out, out, DFF, DM);
}